// round 17
// baseline (speedup 1.0000x reference)
#include <cuda_runtime.h>
#include <cuda_fp16.h>
#include <cstdint>

// Problem constants
#define T_LEN   4096
#define D_DIM   64
#define R_OUT   127
#define HALF_W  63

#define TT      128      // t rows per tile (M)
#define NS      256      // k halo rows staged; rows >= 254 zero
#define SROWS   254

// SMEM: A (16KB) + B (32KB); band (63.5KB) aliases [0,63.5K) after the
// CTA-wide post-compute barrier. 64KB/CTA -> 2 CTAs/SM, ~96KB L1D intact.
#define SM_A      0
#define SM_B      (TT * 128)                 // 16384
#define SM_BAND   0                          // aliased after compute
#define SM_TOTAL  65536

#define SWZ(off) ((off) ^ (((off) >> 3) & 0x70))

// custom B swizzle: pchunk = chunk ^ (((row>>3)&3) | ((row&1)<<2))
static __device__ __forceinline__ uint32_t bswz(uint32_t row) {
    return ((row >> 3) & 3u) | ((row & 1u) << 2);
}

static __device__ __forceinline__ uint32_t smem_u32(const void* p) {
    uint32_t a;
    asm("{ .reg .u64 t; cvta.to.shared.u64 t, %1; cvt.u32.u64 %0, t; }" : "=r"(a) : "l"(p));
    return a;
}

static __device__ __forceinline__ void conv4h(float4 v, uint32_t& h0, uint32_t& h1) {
    __half2 a = __floats2half2_rn(v.x, v.y);
    __half2 b = __floats2half2_rn(v.z, v.w);
    h0 = *reinterpret_cast<uint32_t*>(&a);
    h1 = *reinterpret_cast<uint32_t*>(&b);
}

#define LDSM_X4(r0, r1, r2, r3, a) \
    asm volatile("ldmatrix.sync.aligned.m8n8.x4.shared.b16 {%0,%1,%2,%3}, [%4];" \
        : "=r"(r0), "=r"(r1), "=r"(r2), "=r"(r3) : "r"(a))

#define LDSM_X2(r0, r1, a) \
    asm volatile("ldmatrix.sync.aligned.m8n8.x2.shared.b16 {%0,%1}, [%2];" \
        : "=r"(r0), "=r"(r1) : "r"(a))

#define MMA16816(d, a0, a1, a2, a3, b0, b1) \
    asm volatile("mma.sync.aligned.m16n8k16.row.col.f32.f16.f16.f32 " \
        "{%0,%1,%2,%3}, {%4,%5,%6,%7}, {%8,%9}, {%0,%1,%2,%3};" \
        : "+f"(d[0]), "+f"(d[1]), "+f"(d[2]), "+f"(d[3]) \
        : "r"(a0), "r"(a1), "r"(a2), "r"(a3), "r"(b0), "r"(b1))

__global__ void __launch_bounds__(512, 2)
unfold_dot_hmma(const float* __restrict__ q,
                const float* __restrict__ k,
                float* __restrict__ out)
{
    extern __shared__ char smem[];
    const uint32_t sb = smem_u32(smem);
    const int tid = threadIdx.x;
    const int wid = tid >> 5;
    const int lid = tid & 31;
    const int t0  = blockIdx.x * TT;
    const int bh  = blockIdx.y;
    const int g   = wid >> 2;          // quad index 0..3 (M=32 rows each)
    const int w4  = wid & 3;           // warp within quad
    const int m0  = g * 32;            // 32 output rows per quad

    // ---- stage Q tile: 128 rows x 64 d -> fp16, SW128 ----
    const float4* qg = reinterpret_cast<const float4*>(q) +
                       ((size_t)bh * T_LEN + t0) * (D_DIM / 4);
    #pragma unroll
    for (int it = 0; it < 2; ++it) {
        int idx = tid + it * 512;          // 0..1023
        int row = idx >> 3;
        int gg  = idx & 7;
        float4 v0 = qg[row * 16 + gg * 2];
        float4 v1 = qg[row * 16 + gg * 2 + 1];
        uint32_t h0, h1, h2, h3;
        conv4h(v0, h0, h1);
        conv4h(v1, h2, h3);
        uint32_t off = SWZ((uint32_t)(row * 128 + gg * 16));
        *reinterpret_cast<uint4*>(smem + SM_A + off) = make_uint4(h0, h1, h2, h3);
    }

    // ---- stage K halo: 256 rows (s = t0-63+srow), fp16, bswz swizzle ----
    const float4* kg = reinterpret_cast<const float4*>(k) +
                       (size_t)bh * T_LEN * (D_DIM / 4);
    #pragma unroll
    for (int it = 0; it < 4; ++it) {
        int idx  = tid + it * 512;         // 0..2047
        int srow = idx >> 3;
        int gg   = idx & 7;
        int sg   = t0 - HALF_W + srow;
        float4 v0 = make_float4(0.f, 0.f, 0.f, 0.f);
        float4 v1 = v0;
        if (srow < SROWS && (unsigned)sg < T_LEN) {
            v0 = kg[sg * 16 + gg * 2];
            v1 = kg[sg * 16 + gg * 2 + 1];
        }
        uint32_t h0, h1, h2, h3;
        conv4h(v0, h0, h1);
        conv4h(v1, h2, h3);
        uint32_t off = (uint32_t)(SM_B + srow * 128) + (((uint32_t)gg ^ bswz(srow)) << 4);
        *reinterpret_cast<uint4*>(smem + off) = make_uint4(h0, h1, h2, h3);
    }
    __syncthreads();

    // ---- compute: D = Qh * Kh ----
    // Quad g rows [m0, m0+32) as two m16 blocks sharing B fragments.
    // Quad band cols [m0, m0+160) = 5 supertiles of n32. Warp w4 owns
    // supertile w4 (4 MMAs) + MMA #w4 of shared supertile 4.
    float acc0[5][4], acc1[5][4];
    #pragma unroll
    for (int j = 0; j < 5; ++j)
        #pragma unroll
        for (int e = 0; e < 4; ++e) { acc0[j][e] = 0.f; acc1[j][e] = 0.f; }

    // A lane addresses for the two m16 blocks
    const int amat = lid >> 3;
    const uint32_t a_base0 = (uint32_t)((m0 + (amat & 1) * 8 + (lid & 7)) * 128
                                        + (amat >> 1) * 16);
    // block1 = +16 rows = +2048 bytes: swizzle-invariant

    // B lane constants, own supertile (s = w4)
    const int r7    = lid & 7;
    const int khalf = (lid >> 3) & 1;
    const int phi   = (lid >> 4) & 1;
    const uint32_t row0 = (uint32_t)(m0 + 32 * w4 + 8 * (r7 >> 1) + (r7 & 1) + 2 * phi);
    const uint32_t row1 = row0 + 4;
    const uint32_t swz0 = bswz(row0);
    const uint32_t swz1 = bswz(row1);
    // shared supertile (s = 4), this warp's MMA p = w4 (x2, lanes 0-15)
    const uint32_t rowS = (uint32_t)(m0 + 128 + 8 * (r7 >> 1) + (r7 & 1) + 2 * w4);
    const uint32_t swzS = bswz(rowS);

    #pragma unroll
    for (int kc = 0; kc < 4; ++kc) {
        uint32_t a00, a01, a02, a03, a10, a11, a12, a13;
        uint32_t aoff = SWZ(a_base0 + kc * 32);
        LDSM_X4(a00, a01, a02, a03, sb + SM_A + aoff);            // rows m0..m0+15
        LDSM_X4(a10, a11, a12, a13, sb + SM_A + aoff + 2048);     // rows m0+16..m0+31

        const uint32_t c0 = (uint32_t)(2 * kc + khalf);
        uint32_t ad0 = sb + SM_B + row0 * 128 + ((c0 ^ swz0) << 4);
        uint32_t ad1 = sb + SM_B + row1 * 128 + ((c0 ^ swz1) << 4);

        uint32_t b0, b1, b2, b3;
        LDSM_X4(b0, b1, b2, b3, ad0);                  // own supertile p=0,1
        MMA16816(acc0[0], a00, a01, a02, a03, b0, b1);
        MMA16816(acc1[0], a10, a11, a12, a13, b0, b1);
        MMA16816(acc0[1], a00, a01, a02, a03, b2, b3);
        MMA16816(acc1[1], a10, a11, a12, a13, b2, b3);
        LDSM_X4(b0, b1, b2, b3, ad1);                  // own supertile p=2,3
        MMA16816(acc0[2], a00, a01, a02, a03, b0, b1);
        MMA16816(acc1[2], a10, a11, a12, a13, b0, b1);
        MMA16816(acc0[3], a00, a01, a02, a03, b2, b3);
        MMA16816(acc1[3], a10, a11, a12, a13, b2, b3);
        {   // shared supertile, MMA p = w4
            uint32_t s0, s1;
            uint32_t cS = (uint32_t)(2 * kc + khalf);
            uint32_t adS = sb + SM_B + rowS * 128 + ((cS ^ swzS) << 4);
            LDSM_X2(s0, s1, adS);
            MMA16816(acc0[4], a00, a01, a02, a03, s0, s1);
            MMA16816(acc1[4], a10, a11, a12, a13, s0, s1);
        }
    }

    __syncthreads();   // band aliases operand tiles

    // ---- epilogue: paired scatter into smem band tile ----
    // acc{blk}[p]: lane (a=lid>>2, cb=lid&3, eh) ->
    //   D[i = m0+16blk+a+8eh][col = m0+32*w4+8cb+2p (+1)]   (p<4)
    //   D[i][col = m0+128+8cb+2*w4 (+1)]                     (p==4)
    // band float index: i*126 + col (== i*127 + rr, rr = col - i)
    float* band = reinterpret_cast<float*>(smem + SM_BAND);
    {
        const int a_ln = lid >> 2;
        const int cb   = lid & 3;
        #pragma unroll
        for (int blk = 0; blk < 2; ++blk) {
            const int i0 = m0 + 16 * blk + a_ln;
            #pragma unroll
            for (int p = 0; p < 5; ++p) {
                int col = (p < 4) ? (m0 + 32 * w4 + 8 * cb + 2 * p)
                                  : (m0 + 128 + 8 * cb + 2 * w4);
                const float (*ac)[4] = blk ? acc1 : acc0;
                #pragma unroll
                for (int eh = 0; eh < 2; ++eh) {
                    int i   = i0 + 8 * eh;
                    int idx = i * (R_OUT - 1) + col;
                    unsigned rr = (unsigned)(col - i);
                    float2 v = make_float2(ac[p][2 * eh], ac[p][2 * eh + 1]);
                    if (rr <= 125u) {
                        *reinterpret_cast<float2*>(band + idx) = v;
                    } else if (rr == 126u) {
                        band[idx] = v.x;
                    } else if (rr == 0xFFFFFFFFu) {
                        band[idx + 1] = v.y;
                    }
                }
            }
        }
    }

    // ---- per-quad bulk store: quad's 32 rows = contiguous 16256B slice ----
    asm volatile("bar.sync %0, 128;" :: "r"(1 + g) : "memory");
    if (w4 == 0 && lid == 0) {
        asm volatile("fence.proxy.async.shared::cta;" ::: "memory");
        float* dst = out + ((size_t)bh * T_LEN + t0 + m0) * R_OUT;
        uint32_t src = sb + SM_BAND + (uint32_t)(m0 * R_OUT * 4);
        asm volatile("cp.async.bulk.global.shared::cta.bulk_group [%0], [%1], %2;"
                     :: "l"(dst), "r"(src), "r"((uint32_t)(32 * R_OUT * 4)) : "memory");
        asm volatile("cp.async.bulk.commit_group;" ::: "memory");
        asm volatile("cp.async.bulk.wait_group.read 0;" ::: "memory");
    }
}

extern "C" void kernel_launch(void* const* d_in, const int* in_sizes, int n_in,
                              void* d_out, int out_size)
{
    const float* q = (const float*)d_in[0];
    const float* k = (const float*)d_in[1];
    float* out     = (float*)d_out;

    int bh = in_sizes[0] / (T_LEN * D_DIM);   // 128

    cudaFuncSetAttribute(unfold_dot_hmma,
                         cudaFuncAttributeMaxDynamicSharedMemorySize, SM_TOTAL);

    dim3 grid(T_LEN / TT, bh);                // (32, 128)
    unfold_dot_hmma<<<grid, 512, SM_TOTAL>>>(q, k, out);
}